// round 1
// baseline (speedup 1.0000x reference)
#include <cuda_runtime.h>
#include <math.h>

#define NTOK 13320
#define BATCH 240
#define DM 512
#define DI 2048
#define NH 8
#define DKH 64
#define LNEPS 1e-5f

// ---------------- scratch (static device globals; no allocation) ----------------
__device__ float g_Q[NTOK * DM];
__device__ float g_K[NTOK * DM];
__device__ float g_V[NTOK * DM];
__device__ float g_ctx[NTOK * DM];
__device__ float g_t1[NTOK * DM];
__device__ float g_out1[NTOK * DM];
__device__ float g_h[NTOK * DI];
__device__ int   g_offs[BATCH + 1];

// ---------------- segment offsets (serial scan, 240 elems) ----------------
__global__ void offsets_kernel(const int* __restrict__ num_objs) {
    if (threadIdx.x == 0) {
        int s = 0;
        for (int i = 0; i < BATCH; i++) { g_offs[i] = s; s += num_objs[i]; }
        g_offs[BATCH] = s;
    }
}

// ---------------- classic fp32 SGEMM: C = A[MxK] @ B[KxN] + bias (+resid) (relu) ----------------
template <bool RELU, bool RESID>
__global__ __launch_bounds__(256) void sgemm_kernel(
    const float* __restrict__ A, const float* __restrict__ B,
    const float* __restrict__ bias, const float* __restrict__ R,
    float* __restrict__ C, int M, int K, int N)
{
    const int BM = 128, BN = 128, BK = 8;
    __shared__ float As[BK][BM];
    __shared__ float Bs[BK][BN];

    int tid = threadIdx.x;
    int bm = blockIdx.y * BM;
    int bn = blockIdx.x * BN;
    int tx = tid & 15;      // 0..15 -> col group
    int ty = tid >> 4;      // 0..15 -> row group

    float acc[8][8];
#pragma unroll
    for (int i = 0; i < 8; i++)
#pragma unroll
        for (int j = 0; j < 8; j++) acc[i][j] = 0.f;

    int arow = tid >> 1;            // 0..127
    int acol = (tid & 1) * 4;       // 0 or 4
    int brow = tid >> 5;            // 0..7
    int bcol = (tid & 31) * 4;      // 0..124

    int agrow = bm + arow; if (agrow > M - 1) agrow = M - 1;
    const float* Aptr = A + (long)agrow * K + acol;
    const float* Bptr = B + (long)brow * N + bn + bcol;

    for (int k0 = 0; k0 < K; k0 += BK) {
        float4 av = *(const float4*)(Aptr + k0);
        As[acol + 0][arow] = av.x;
        As[acol + 1][arow] = av.y;
        As[acol + 2][arow] = av.z;
        As[acol + 3][arow] = av.w;
        float4 bv = *(const float4*)(Bptr + (long)k0 * N);
        *(float4*)&Bs[brow][bcol] = bv;
        __syncthreads();

#pragma unroll
        for (int kk = 0; kk < BK; kk++) {
            float a[8], b[8];
            *(float4*)&a[0] = *(const float4*)&As[kk][ty * 8];
            *(float4*)&a[4] = *(const float4*)&As[kk][ty * 8 + 4];
            *(float4*)&b[0] = *(const float4*)&Bs[kk][tx * 8];
            *(float4*)&b[4] = *(const float4*)&Bs[kk][tx * 8 + 4];
#pragma unroll
            for (int i = 0; i < 8; i++)
#pragma unroll
                for (int j = 0; j < 8; j++)
                    acc[i][j] = fmaf(a[i], b[j], acc[i][j]);
        }
        __syncthreads();
    }

#pragma unroll
    for (int i = 0; i < 8; i++) {
        int row = bm + ty * 8 + i;
        if (row >= M) continue;
#pragma unroll
        for (int j = 0; j < 8; j += 4) {
            int col = bn + tx * 8 + j;
            float4 v;
            v.x = acc[i][j + 0] + bias[col + 0];
            v.y = acc[i][j + 1] + bias[col + 1];
            v.z = acc[i][j + 2] + bias[col + 2];
            v.w = acc[i][j + 3] + bias[col + 3];
            if (RESID) {
                float4 r = *(const float4*)(R + (long)row * N + col);
                v.x += r.x; v.y += r.y; v.z += r.z; v.w += r.w;
            }
            if (RELU) {
                v.x = fmaxf(v.x, 0.f); v.y = fmaxf(v.y, 0.f);
                v.z = fmaxf(v.z, 0.f); v.w = fmaxf(v.w, 0.f);
            }
            *(float4*)(C + (long)row * N + col) = v;
        }
    }
}

// ---------------- LayerNorm over D=512, one block (128 thr) per row ----------------
template <bool ACC>
__global__ __launch_bounds__(128) void ln_kernel(
    const float* __restrict__ X, const float* __restrict__ g,
    const float* __restrict__ b, float* __restrict__ out)
{
    int row = blockIdx.x;
    int tid = threadIdx.x;
    const float4* x4 = (const float4*)(X + (long)row * DM);
    float4 v = x4[tid];

    __shared__ float sbuf[8];
    int wid = tid >> 5, lane = tid & 31;

    float s = v.x + v.y + v.z + v.w;
#pragma unroll
    for (int o = 16; o > 0; o >>= 1) s += __shfl_xor_sync(0xffffffffu, s, o);
    if (lane == 0) sbuf[wid] = s;
    __syncthreads();
    float mean = (sbuf[0] + sbuf[1] + sbuf[2] + sbuf[3]) * (1.0f / DM);
    __syncthreads();

    float dx0 = v.x - mean, dx1 = v.y - mean, dx2 = v.z - mean, dx3 = v.w - mean;
    float sq = dx0 * dx0 + dx1 * dx1 + dx2 * dx2 + dx3 * dx3;
#pragma unroll
    for (int o = 16; o > 0; o >>= 1) sq += __shfl_xor_sync(0xffffffffu, sq, o);
    if (lane == 0) sbuf[wid] = sq;
    __syncthreads();
    float var = (sbuf[0] + sbuf[1] + sbuf[2] + sbuf[3]) * (1.0f / DM);
    float rstd = rsqrtf(var + LNEPS);

    float4 gg = ((const float4*)g)[tid];
    float4 bb = ((const float4*)b)[tid];
    float4 y;
    y.x = dx0 * rstd * gg.x + bb.x;
    y.y = dx1 * rstd * gg.y + bb.y;
    y.z = dx2 * rstd * gg.z + bb.z;
    y.w = dx3 * rstd * gg.w + bb.w;

    float4* o4 = (float4*)(out + (long)row * DM);
    if (ACC) {
        float4 prev = o4[tid];
        y.x += prev.x; y.y += prev.y; y.z += prev.z; y.w += prev.w;
    }
    o4[tid] = y;
}

// ---------------- segment attention: one block per (segment, head), online softmax ----------------
__global__ __launch_bounds__(96) void attn_kernel()
{
    int s = blockIdx.x;
    int h = blockIdx.y;
    int off = g_offs[s];
    int L = g_offs[s + 1] - off;

    __shared__ float Ks[95 * DKH];
    for (int idx = threadIdx.x; idx < L * DKH; idx += 96) {
        int j = idx >> 6, d = idx & 63;
        Ks[idx] = g_K[(long)(off + j) * DM + h * DKH + d];
    }
    __syncthreads();

    int i = threadIdx.x;
    if (i >= L) return;

    float q[DKH];
    const float4* qp = (const float4*)(g_Q + (long)(off + i) * DM + h * DKH);
#pragma unroll
    for (int t = 0; t < 16; t++) {
        float4 u = qp[t];
        q[4 * t + 0] = u.x; q[4 * t + 1] = u.y; q[4 * t + 2] = u.z; q[4 * t + 3] = u.w;
    }

    float m = -INFINITY, l = 0.f;
    float acc[DKH];
#pragma unroll
    for (int d = 0; d < DKH; d++) acc[d] = 0.f;

    for (int j = 0; j < L; j++) {
        const float4* kr = (const float4*)&Ks[j * DKH];
        float sd = 0.f;
#pragma unroll
        for (int t = 0; t < 16; t++) {
            float4 kv = kr[t];
            sd = fmaf(q[4 * t + 0], kv.x, sd);
            sd = fmaf(q[4 * t + 1], kv.y, sd);
            sd = fmaf(q[4 * t + 2], kv.z, sd);
            sd = fmaf(q[4 * t + 3], kv.w, sd);
        }
        sd *= 0.125f;  // 1/sqrt(64)

        float mn = fmaxf(m, sd);
        float corr = expf(m - mn);   // exp(-inf)=0 on first iter
        float p = expf(sd - mn);
        l = l * corr + p;
        const float4* vr = (const float4*)(g_V + (long)(off + j) * DM + h * DKH);
#pragma unroll
        for (int t = 0; t < 16; t++) {
            float4 vv = vr[t];
            acc[4 * t + 0] = acc[4 * t + 0] * corr + p * vv.x;
            acc[4 * t + 1] = acc[4 * t + 1] * corr + p * vv.y;
            acc[4 * t + 2] = acc[4 * t + 2] * corr + p * vv.z;
            acc[4 * t + 3] = acc[4 * t + 3] * corr + p * vv.w;
        }
        m = mn;
    }

    float inv = 1.0f / l;
    float4* o = (float4*)(g_ctx + (long)(off + i) * DM + h * DKH);
#pragma unroll
    for (int t = 0; t < 16; t++) {
        float4 y;
        y.x = acc[4 * t + 0] * inv; y.y = acc[4 * t + 1] * inv;
        y.z = acc[4 * t + 2] * inv; y.w = acc[4 * t + 3] * inv;
        o[t] = y;
    }
}

// ---------------- host ----------------
extern "C" void kernel_launch(void* const* d_in, const int* in_sizes, int n_in,
                              void* d_out, int out_size)
{
    const float* vis  = (const float*)d_in[0];
    const float* txt  = (const float*)d_in[1];
    const float* Wq   = (const float*)d_in[2];
    const float* bq   = (const float*)d_in[3];
    const float* Wk   = (const float*)d_in[4];
    const float* bk   = (const float*)d_in[5];
    const float* Wv   = (const float*)d_in[6];
    const float* bv   = (const float*)d_in[7];
    const float* Wo   = (const float*)d_in[8];
    const float* bo   = (const float*)d_in[9];
    const float* g1   = (const float*)d_in[10];
    const float* be1  = (const float*)d_in[11];
    const float* W1   = (const float*)d_in[12];
    const float* b1   = (const float*)d_in[13];
    const float* W2   = (const float*)d_in[14];
    const float* b2   = (const float*)d_in[15];
    const float* g2   = (const float*)d_in[16];
    const float* be2  = (const float*)d_in[17];
    const int*   nobj = (const int*)d_in[18];
    float* out = (float*)d_out;

    float *Q, *K, *V, *CTX, *T1, *OUT1, *H;
    cudaGetSymbolAddress((void**)&Q, g_Q);
    cudaGetSymbolAddress((void**)&K, g_K);
    cudaGetSymbolAddress((void**)&V, g_V);
    cudaGetSymbolAddress((void**)&CTX, g_ctx);
    cudaGetSymbolAddress((void**)&T1, g_t1);
    cudaGetSymbolAddress((void**)&OUT1, g_out1);
    cudaGetSymbolAddress((void**)&H, g_h);

    offsets_kernel<<<1, 32>>>(nobj);

    const int MT = (NTOK + 127) / 128;  // 105
    dim3 gN512(DM / 128, MT);           // (4, 105)
    dim3 gN2048(DI / 128, MT);          // (16, 105)
    dim3 gAttn(BATCH, NH);

    // encoders: (q_src, kv_src, param layer, out region, first-writer?)
    struct Enc { const float* qs; const float* kv; int p; float* reg; bool first; };
    Enc encs[4] = {
        { vis, vis, 0, out,              true  },   // vsa
        { vis, txt, 2, out,              false },   // vca
        { txt, txt, 1, out + (long)NTOK * DM, true  },   // tsa
        { txt, vis, 3, out + (long)NTOK * DM, false },   // tca
    };

    for (int e = 0; e < 4; e++) {
        const float* qs = encs[e].qs;
        const float* kv = encs[e].kv;
        int p = encs[e].p;
        float* reg = encs[e].reg;

        const float* Wq_p = Wq + (long)p * DM * DM;
        const float* Wk_p = Wk + (long)p * DM * DM;
        const float* Wv_p = Wv + (long)p * DM * DM;
        const float* Wo_p = Wo + (long)p * DM * DM;
        const float* W1_p = W1 + (long)p * DM * DI;
        const float* W2_p = W2 + (long)p * DI * DM;

        sgemm_kernel<false, false><<<gN512, 256>>>(qs, Wq_p, bq + p * DM, nullptr, Q, NTOK, DM, DM);
        sgemm_kernel<false, false><<<gN512, 256>>>(kv, Wk_p, bk + p * DM, nullptr, K, NTOK, DM, DM);
        sgemm_kernel<false, false><<<gN512, 256>>>(kv, Wv_p, bv + p * DM, nullptr, V, NTOK, DM, DM);

        attn_kernel<<<gAttn, 96>>>();

        // t1 = ctx @ Wo + bo + q_src ; out1 = LN1(t1)
        sgemm_kernel<false, true><<<gN512, 256>>>(CTX, Wo_p, bo + p * DM, qs, T1, NTOK, DM, DM);
        ln_kernel<false><<<NTOK, 128>>>(T1, g1 + p * DM, be1 + p * DM, OUT1);

        // h = relu(out1 @ W1 + b1) ; t1 = h @ W2 + b2 + out1 ; region (+)= LN2(t1)
        sgemm_kernel<true, false><<<gN2048, 256>>>(OUT1, W1_p, b1 + p * DI, nullptr, H, NTOK, DM, DI);
        sgemm_kernel<false, true><<<gN512, 256>>>(H, W2_p, b2 + p * DM, OUT1, T1, NTOK, DI, DM);
        if (encs[e].first)
            ln_kernel<false><<<NTOK, 128>>>(T1, g2 + p * DM, be2 + p * DM, reg);
        else
            ln_kernel<true><<<NTOK, 128>>>(T1, g2 + p * DM, be2 + p * DM, reg);
    }
}

// round 3
// speedup vs baseline: 3.2636x; 3.2636x over previous
#include <cuda_runtime.h>
#include <math.h>
#include <stdint.h>

#define NTOK 13320
#define BATCH 240
#define DM 512
#define DI 2048
#define NH 8
#define DKH 64
#define LNEPS 1e-5f

// ================= scratch (static device globals; no allocation) =================
__device__ float g_Q[NTOK * DM];
__device__ float g_K[NTOK * DM];
__device__ float g_V[NTOK * DM];
__device__ float g_ctx[NTOK * DM];
__device__ float g_t1[NTOK * DM];
__device__ float g_out1[NTOK * DM];
__device__ float g_h[NTOK * DI];
__device__ int   g_offs[BATCH + 1];
// transposed weights (N x K, K-major rows), tf32-rounded, per encoder layer p=0..3
__device__ float g_WqT[4 * DM * DM];
__device__ float g_WkT[4 * DM * DM];
__device__ float g_WvT[4 * DM * DM];
__device__ float g_WoT[4 * DM * DM];
__device__ float g_W1T[4 * DI * DM];
__device__ float g_W2T[4 * DM * DI];

// ================= helpers =================
__device__ __forceinline__ uint32_t smem_u32(const void* p) {
    uint32_t a;
    asm("{ .reg .u64 t; cvta.to.shared.u64 t, %1; cvt.u32.u64 %0, t; }" : "=r"(a) : "l"(p));
    return a;
}
__device__ __forceinline__ void cp_async16(uint32_t dst, const void* src) {
    asm volatile("cp.async.cg.shared.global [%0], [%1], 16;" :: "r"(dst), "l"(src));
}
#define CP_COMMIT() asm volatile("cp.async.commit_group;" ::: "memory")
#define CP_WAIT(n)  asm volatile("cp.async.wait_group %0;" :: "n"(n) : "memory")

__device__ __forceinline__ uint32_t tf32_rna(float f) {
    uint32_t r;
    asm("cvt.rna.tf32.f32 %0, %1;" : "=r"(r) : "f"(f));
    return r;
}
__device__ __forceinline__ void ldmatrix_x4(uint32_t& r0, uint32_t& r1, uint32_t& r2, uint32_t& r3, uint32_t addr) {
    asm volatile("ldmatrix.sync.aligned.m8n8.x4.shared.b16 {%0,%1,%2,%3}, [%4];"
        : "=r"(r0), "=r"(r1), "=r"(r2), "=r"(r3) : "r"(addr));
}
__device__ __forceinline__ void mma_tf32(float* d, const uint32_t* a, const uint32_t* b) {
    asm volatile("mma.sync.aligned.m16n8k8.row.col.f32.tf32.tf32.f32 "
        "{%0,%1,%2,%3}, {%4,%5,%6,%7}, {%8,%9}, {%0,%1,%2,%3};"
        : "+f"(d[0]), "+f"(d[1]), "+f"(d[2]), "+f"(d[3])
        : "r"(a[0]), "r"(a[1]), "r"(a[2]), "r"(a[3]), "r"(b[0]), "r"(b[1]));
}

// ================= segment offsets =================
__global__ void offsets_kernel(const int* __restrict__ num_objs) {
    if (threadIdx.x == 0) {
        int s = 0;
        for (int i = 0; i < BATCH; i++) { g_offs[i] = s; s += num_objs[i]; }
        g_offs[BATCH] = s;
    }
}

// ======== weight transpose: S[R x C] -> D[C x R], rounded to tf32 (rna) ========
__global__ __launch_bounds__(256) void transpose_kernel(const float* __restrict__ S, float* __restrict__ D,
                                                        int R, int C) {
    __shared__ float t[32][33];
    int bx = blockIdx.x * 32;
    int by = blockIdx.y * 32;
    int x = bx + threadIdx.x;
#pragma unroll
    for (int yy = threadIdx.y; yy < 32; yy += 8)
        t[yy][threadIdx.x] = S[(size_t)(by + yy) * C + x];
    __syncthreads();
    int x2 = by + threadIdx.x;
#pragma unroll
    for (int yy = threadIdx.y; yy < 32; yy += 8)
        D[(size_t)(bx + yy) * R + x2] = __uint_as_float(tf32_rna(t[threadIdx.x][yy]));
}

// ======== tf32 mma.sync GEMM: C = A[MxK] @ Bt[NxK]^T + bias (+R) (relu) ========
// CTA tile 128x128, BK=32, 2-stage cp.async double buffer, 8 warps of 64x32.
#define BKF 32                     // k floats per stage
#define LDS_STRIDE 36              // padded row stride (floats)
#define TILE_BYTES (128 * LDS_STRIDE * 4)       // 18432 per matrix
#define STAGE_BYTES (2 * TILE_BYTES)            // A + B
#define GEMM_SMEM (2 * STAGE_BYTES)             // 73728

template <bool RELU, bool RESID>
__global__ __launch_bounds__(256) void gemm_tc(
    const float* __restrict__ A, const float* __restrict__ Bt,
    const float* __restrict__ bias, const float* __restrict__ R,
    float* __restrict__ C, int M, int K, int N)
{
    extern __shared__ char smem[];
    const uint32_t sb = smem_u32(smem);
    const int tid = threadIdx.x;
    const int wid = tid >> 5;
    const int lane = tid & 31;
    const int m0 = blockIdx.y * 128;
    const int n0 = blockIdx.x * 128;
    const int warp_m = wid & 1;          // 0..1 -> 64-row band
    const int warp_n = wid >> 1;         // 0..3 -> 32-col band

    float acc[4][4][4];
#pragma unroll
    for (int i = 0; i < 4; i++)
#pragma unroll
        for (int j = 0; j < 4; j++)
#pragma unroll
            for (int r = 0; r < 4; r++) acc[i][j][r] = 0.f;

    // per-thread ldmatrix address components
    const int mtx = lane >> 3;           // matrix index 0..3
    const int mr  = lane & 7;            // row within matrix
    const int a_row = (mtx & 1) * 8 + mr;
    const int a_col = (mtx >> 1) * 4;
    const int b_row = (mtx >> 1) * 8 + mr;
    const int b_col = (mtx & 1) * 4;

    const int KT = K >> 5;

    // stage loader: 4 A chunks + 4 B chunks of 16B per thread
    auto load_stage = [&](int s, int kiter) {
        const int k0 = kiter << 5;
        const uint32_t base = sb + (uint32_t)s * STAGE_BYTES;
#pragma unroll
        for (int i = 0; i < 4; i++) {
            int c = tid + i * 256;               // 0..1023
            int row = c >> 3, k16 = c & 7;
            int gr = m0 + row; gr = gr < M ? gr : M - 1;
            cp_async16(base + row * (LDS_STRIDE * 4) + k16 * 16,
                       A + (size_t)gr * K + k0 + k16 * 4);
        }
#pragma unroll
        for (int i = 0; i < 4; i++) {
            int c = tid + i * 256;
            int row = c >> 3, k16 = c & 7;
            cp_async16(base + TILE_BYTES + row * (LDS_STRIDE * 4) + k16 * 16,
                       Bt + (size_t)(n0 + row) * K + k0 + k16 * 4);
        }
        CP_COMMIT();
    };

    load_stage(0, 0);

    for (int it = 0; it < KT; it++) {
        if (it + 1 < KT) {
            load_stage((it + 1) & 1, it + 1);
            CP_WAIT(1);
        } else {
            CP_WAIT(0);
        }
        __syncthreads();

        const uint32_t abase = sb + (uint32_t)(it & 1) * STAGE_BYTES;
        const uint32_t bbase = abase + TILE_BYTES;

#pragma unroll
        for (int kk = 0; kk < 4; kk++) {
            // A fragments: 4 m-frags (m16), cvt.rna to tf32
            uint32_t af[4][4];
#pragma unroll
            for (int mi = 0; mi < 4; mi++) {
                uint32_t addr = abase +
                    ((warp_m * 64 + mi * 16 + a_row) * LDS_STRIDE + kk * 8 + a_col) * 4;
                ldmatrix_x4(af[mi][0], af[mi][1], af[mi][2], af[mi][3], addr);
#pragma unroll
                for (int r = 0; r < 4; r++)
                    af[mi][r] = tf32_rna(__uint_as_float(af[mi][r]));
            }
            // B fragments: 4 n-frags via 2 x4 loads (B pre-rounded)
            uint32_t bf[4][2];
#pragma unroll
            for (int nj2 = 0; nj2 < 2; nj2++) {
                uint32_t addr = bbase +
                    ((warp_n * 32 + nj2 * 16 + b_row) * LDS_STRIDE + kk * 8 + b_col) * 4;
                uint32_t r0, r1, r2, r3;
                ldmatrix_x4(r0, r1, r2, r3, addr);
                bf[nj2 * 2 + 0][0] = r0; bf[nj2 * 2 + 0][1] = r1;
                bf[nj2 * 2 + 1][0] = r2; bf[nj2 * 2 + 1][1] = r3;
            }
#pragma unroll
            for (int mi = 0; mi < 4; mi++)
#pragma unroll
                for (int nj = 0; nj < 4; nj++)
                    mma_tf32(acc[mi][nj], af[mi], bf[nj]);
        }
        __syncthreads();
    }

    // ---- epilogue: c-frag mapping m16n8 f32 ----
    const int er = lane >> 2;            // 0..7
    const int ec = (lane & 3) * 2;       // 0,2,4,6
#pragma unroll
    for (int mi = 0; mi < 4; mi++) {
#pragma unroll
        for (int half = 0; half < 2; half++) {
            int row = m0 + warp_m * 64 + mi * 16 + half * 8 + er;
            if (row >= M) continue;
#pragma unroll
            for (int nj = 0; nj < 4; nj++) {
                int col = n0 + warp_n * 32 + nj * 8 + ec;
                float2 v;
                v.x = acc[mi][nj][half * 2 + 0] + bias[col + 0];
                v.y = acc[mi][nj][half * 2 + 1] + bias[col + 1];
                if (RESID) {
                    const float2 rv = *(const float2*)(R + (size_t)row * N + col);
                    v.x += rv.x; v.y += rv.y;
                }
                if (RELU) { v.x = fmaxf(v.x, 0.f); v.y = fmaxf(v.y, 0.f); }
                *(float2*)(C + (size_t)row * N + col) = v;
            }
        }
    }
}

// ================= LayerNorm over D=512 =================
template <bool ACC>
__global__ __launch_bounds__(128) void ln_kernel(
    const float* __restrict__ X, const float* __restrict__ g,
    const float* __restrict__ b, float* __restrict__ out)
{
    int row = blockIdx.x;
    int tid = threadIdx.x;
    const float4* x4 = (const float4*)(X + (size_t)row * DM);
    float4 v = x4[tid];

    __shared__ float sbuf[8];
    int wid = tid >> 5, lane = tid & 31;

    float s = v.x + v.y + v.z + v.w;
#pragma unroll
    for (int o = 16; o > 0; o >>= 1) s += __shfl_xor_sync(0xffffffffu, s, o);
    if (lane == 0) sbuf[wid] = s;
    __syncthreads();
    float mean = (sbuf[0] + sbuf[1] + sbuf[2] + sbuf[3]) * (1.0f / DM);
    __syncthreads();

    float dx0 = v.x - mean, dx1 = v.y - mean, dx2 = v.z - mean, dx3 = v.w - mean;
    float sq = dx0 * dx0 + dx1 * dx1 + dx2 * dx2 + dx3 * dx3;
#pragma unroll
    for (int o = 16; o > 0; o >>= 1) sq += __shfl_xor_sync(0xffffffffu, sq, o);
    if (lane == 0) sbuf[wid] = sq;
    __syncthreads();
    float var = (sbuf[0] + sbuf[1] + sbuf[2] + sbuf[3]) * (1.0f / DM);
    float rstd = rsqrtf(var + LNEPS);

    float4 gg = ((const float4*)g)[tid];
    float4 bb = ((const float4*)b)[tid];
    float4 y;
    y.x = dx0 * rstd * gg.x + bb.x;
    y.y = dx1 * rstd * gg.y + bb.y;
    y.z = dx2 * rstd * gg.z + bb.z;
    y.w = dx3 * rstd * gg.w + bb.w;

    float4* o4 = (float4*)(out + (size_t)row * DM);
    if (ACC) {
        float4 prev = o4[tid];
        y.x += prev.x; y.y += prev.y; y.z += prev.z; y.w += prev.w;
    }
    o4[tid] = y;
}

// ================= segment attention (K and V cached in SMEM) =================
__global__ __launch_bounds__(96) void attn_kernel()
{
    int s = blockIdx.x;
    int h = blockIdx.y;
    int off = g_offs[s];
    int L = g_offs[s + 1] - off;

    __shared__ float Ks[95 * DKH];
    __shared__ float Vs[95 * DKH];
    for (int idx = threadIdx.x; idx < L * DKH; idx += 96) {
        int j = idx >> 6, d = idx & 63;
        Ks[idx] = g_K[(size_t)(off + j) * DM + h * DKH + d];
        Vs[idx] = g_V[(size_t)(off + j) * DM + h * DKH + d];
    }
    __syncthreads();

    int i = threadIdx.x;
    if (i >= L) return;

    float q[DKH];
    const float4* qp = (const float4*)(g_Q + (size_t)(off + i) * DM + h * DKH);
#pragma unroll
    for (int t = 0; t < 16; t++) {
        float4 u = qp[t];
        q[4 * t + 0] = u.x; q[4 * t + 1] = u.y; q[4 * t + 2] = u.z; q[4 * t + 3] = u.w;
    }

    float m = -INFINITY, l = 0.f;
    float acc[DKH];
#pragma unroll
    for (int d = 0; d < DKH; d++) acc[d] = 0.f;

    for (int j = 0; j < L; j++) {
        const float4* kr = (const float4*)&Ks[j * DKH];
        float sd = 0.f;
#pragma unroll
        for (int t = 0; t < 16; t++) {
            float4 kv = kr[t];
            sd = fmaf(q[4 * t + 0], kv.x, sd);
            sd = fmaf(q[4 * t + 1], kv.y, sd);
            sd = fmaf(q[4 * t + 2], kv.z, sd);
            sd = fmaf(q[4 * t + 3], kv.w, sd);
        }
        sd *= 0.125f;

        float mn = fmaxf(m, sd);
        float corr = expf(m - mn);
        float p = expf(sd - mn);
        l = l * corr + p;
        const float4* vr = (const float4*)&Vs[j * DKH];
#pragma unroll
        for (int t = 0; t < 16; t++) {
            float4 vv = vr[t];
            acc[4 * t + 0] = acc[4 * t + 0] * corr + p * vv.x;
            acc[4 * t + 1] = acc[4 * t + 1] * corr + p * vv.y;
            acc[4 * t + 2] = acc[4 * t + 2] * corr + p * vv.z;
            acc[4 * t + 3] = acc[4 * t + 3] * corr + p * vv.w;
        }
        m = mn;
    }

    float inv = 1.0f / l;
    float4* o = (float4*)(g_ctx + (size_t)(off + i) * DM + h * DKH);
#pragma unroll
    for (int t = 0; t < 16; t++) {
        float4 y;
        y.x = acc[4 * t + 0] * inv; y.y = acc[4 * t + 1] * inv;
        y.z = acc[4 * t + 2] * inv; y.w = acc[4 * t + 3] * inv;
        o[t] = y;
    }
}

// ================= host =================
extern "C" void kernel_launch(void* const* d_in, const int* in_sizes, int n_in,
                              void* d_out, int out_size)
{
    const float* vis  = (const float*)d_in[0];
    const float* txt  = (const float*)d_in[1];
    const float* Wq   = (const float*)d_in[2];
    const float* bq   = (const float*)d_in[3];
    const float* Wk   = (const float*)d_in[4];
    const float* bk   = (const float*)d_in[5];
    const float* Wv   = (const float*)d_in[6];
    const float* bv   = (const float*)d_in[7];
    const float* Wo   = (const float*)d_in[8];
    const float* bo   = (const float*)d_in[9];
    const float* g1   = (const float*)d_in[10];
    const float* be1  = (const float*)d_in[11];
    const float* W1   = (const float*)d_in[12];
    const float* b1   = (const float*)d_in[13];
    const float* W2   = (const float*)d_in[14];
    const float* b2   = (const float*)d_in[15];
    const float* g2   = (const float*)d_in[16];
    const float* be2  = (const float*)d_in[17];
    const int*   nobj = (const int*)d_in[18];
    float* out = (float*)d_out;

    float *Q, *K, *V, *CTX, *T1, *OUT1, *H;
    float *WqT, *WkT, *WvT, *WoT, *W1T, *W2T;
    cudaGetSymbolAddress((void**)&Q, g_Q);
    cudaGetSymbolAddress((void**)&K, g_K);
    cudaGetSymbolAddress((void**)&V, g_V);
    cudaGetSymbolAddress((void**)&CTX, g_ctx);
    cudaGetSymbolAddress((void**)&T1, g_t1);
    cudaGetSymbolAddress((void**)&OUT1, g_out1);
    cudaGetSymbolAddress((void**)&H, g_h);
    cudaGetSymbolAddress((void**)&WqT, g_WqT);
    cudaGetSymbolAddress((void**)&WkT, g_WkT);
    cudaGetSymbolAddress((void**)&WvT, g_WvT);
    cudaGetSymbolAddress((void**)&WoT, g_WoT);
    cudaGetSymbolAddress((void**)&W1T, g_W1T);
    cudaGetSymbolAddress((void**)&W2T, g_W2T);

    cudaFuncSetAttribute(gemm_tc<false, false>, cudaFuncAttributeMaxDynamicSharedMemorySize, GEMM_SMEM);
    cudaFuncSetAttribute(gemm_tc<false, true>,  cudaFuncAttributeMaxDynamicSharedMemorySize, GEMM_SMEM);
    cudaFuncSetAttribute(gemm_tc<true, false>,  cudaFuncAttributeMaxDynamicSharedMemorySize, GEMM_SMEM);

    offsets_kernel<<<1, 32>>>(nobj);

    dim3 tb(32, 8);
    for (int p = 0; p < 4; p++) {
        dim3 g512(DM / 32, DM / 32);
        transpose_kernel<<<g512, tb>>>(Wq + (size_t)p * DM * DM, WqT + (size_t)p * DM * DM, DM, DM);
        transpose_kernel<<<g512, tb>>>(Wk + (size_t)p * DM * DM, WkT + (size_t)p * DM * DM, DM, DM);
        transpose_kernel<<<g512, tb>>>(Wv + (size_t)p * DM * DM, WvT + (size_t)p * DM * DM, DM, DM);
        transpose_kernel<<<g512, tb>>>(Wo + (size_t)p * DM * DM, WoT + (size_t)p * DM * DM, DM, DM);
        dim3 gW1(DI / 32, DM / 32);
        transpose_kernel<<<gW1, tb>>>(W1 + (size_t)p * DM * DI, W1T + (size_t)p * DI * DM, DM, DI);
        dim3 gW2(DM / 32, DI / 32);
        transpose_kernel<<<gW2, tb>>>(W2 + (size_t)p * DI * DM, W2T + (size_t)p * DM * DI, DI, DM);
    }

    const int MT = (NTOK + 127) / 128;  // 105
    dim3 gN512(DM / 128, MT);           // (4, 105)
    dim3 gN2048(DI / 128, MT);          // (16, 105)
    dim3 gAttn(BATCH, NH);

    struct Enc { const float* qs; const float* kv; int p; float* reg; bool first; };
    Enc encs[4] = {
        { vis, vis, 0, out,                     true  },
        { vis, txt, 2, out,                     false },
        { txt, txt, 1, out + (size_t)NTOK * DM, true  },
        { txt, vis, 3, out + (size_t)NTOK * DM, false },
    };

    for (int e = 0; e < 4; e++) {
        const float* qs = encs[e].qs;
        const float* kv = encs[e].kv;
        int p = encs[e].p;
        float* reg = encs[e].reg;

        const float* WqTp = WqT + (size_t)p * DM * DM;
        const float* WkTp = WkT + (size_t)p * DM * DM;
        const float* WvTp = WvT + (size_t)p * DM * DM;
        const float* WoTp = WoT + (size_t)p * DM * DM;
        const float* W1Tp = W1T + (size_t)p * DI * DM;
        const float* W2Tp = W2T + (size_t)p * DM * DI;

        gemm_tc<false, false><<<gN512, 256, GEMM_SMEM>>>(qs, WqTp, bq + p * DM, nullptr, Q, NTOK, DM, DM);
        gemm_tc<false, false><<<gN512, 256, GEMM_SMEM>>>(kv, WkTp, bk + p * DM, nullptr, K, NTOK, DM, DM);
        gemm_tc<false, false><<<gN512, 256, GEMM_SMEM>>>(kv, WvTp, bv + p * DM, nullptr, V, NTOK, DM, DM);

        attn_kernel<<<gAttn, 96>>>();

        gemm_tc<false, true><<<gN512, 256, GEMM_SMEM>>>(CTX, WoTp, bo + p * DM, qs, T1, NTOK, DM, DM);
        ln_kernel<false><<<NTOK, 128>>>(T1, g1 + p * DM, be1 + p * DM, OUT1);

        gemm_tc<true, false><<<gN2048, 256, GEMM_SMEM>>>(OUT1, W1Tp, b1 + p * DI, nullptr, H, NTOK, DM, DI);
        gemm_tc<false, true><<<gN512, 256, GEMM_SMEM>>>(H, W2Tp, b2 + p * DM, OUT1, T1, NTOK, DI, DM);
        if (encs[e].first)
            ln_kernel<false><<<NTOK, 128>>>(T1, g2 + p * DM, be2 + p * DM, reg);
        else
            ln_kernel<true><<<NTOK, 128>>>(T1, g2 + p * DM, be2 + p * DM, reg);
    }
}

// round 4
// speedup vs baseline: 4.7279x; 1.4487x over previous
#include <cuda_runtime.h>
#include <cuda_bf16.h>
#include <math.h>
#include <stdint.h>

#define NTOK 13320
#define BATCH 240
#define DM 512
#define DI 2048
#define NH 8
#define DKH 64
#define LNEPS 1e-5f

// ================= scratch (static device globals; no allocation) =================
__device__ float g_Q [NTOK * DM];
__device__ float g_KV[NTOK * 2 * DM];          // [K | V] per row, N=1024
__device__ float g_t1[NTOK * DM];
__device__ float g_out1[NTOK * DM];
__device__ int   g_offs[BATCH + 1];
__device__ float g_bkv[4 * 2 * DM];

__device__ __nv_bfloat16 g_visb [NTOK * DM];
__device__ __nv_bfloat16 g_txtb [NTOK * DM];
__device__ __nv_bfloat16 g_ctxb [NTOK * DM];
__device__ __nv_bfloat16 g_out1b[NTOK * DM];
__device__ __nv_bfloat16 g_hb   [NTOK * DI];

__device__ __nv_bfloat16 g_WqT [4 * DM * DM];
__device__ __nv_bfloat16 g_WkvT[4 * 2 * DM * DM];
__device__ __nv_bfloat16 g_WoT [4 * DM * DM];
__device__ __nv_bfloat16 g_W1T [4 * DI * DM];
__device__ __nv_bfloat16 g_W2T [4 * DM * DI];

// ================= helpers =================
__device__ __forceinline__ uint32_t smem_u32(const void* p) {
    uint32_t a;
    asm("{ .reg .u64 t; cvta.to.shared.u64 t, %1; cvt.u32.u64 %0, t; }" : "=r"(a) : "l"(p));
    return a;
}
__device__ __forceinline__ void cp_async16(uint32_t dst, const void* src) {
    asm volatile("cp.async.cg.shared.global [%0], [%1], 16;" :: "r"(dst), "l"(src));
}
#define CP_COMMIT() asm volatile("cp.async.commit_group;" ::: "memory")
#define CP_WAIT(n)  asm volatile("cp.async.wait_group %0;" :: "n"(n) : "memory")

__device__ __forceinline__ void ldmatrix_x4(uint32_t& r0, uint32_t& r1, uint32_t& r2, uint32_t& r3, uint32_t addr) {
    asm volatile("ldmatrix.sync.aligned.m8n8.x4.shared.b16 {%0,%1,%2,%3}, [%4];"
        : "=r"(r0), "=r"(r1), "=r"(r2), "=r"(r3) : "r"(addr));
}
__device__ __forceinline__ void mma_bf16(float* d, const uint32_t* a, const uint32_t* b) {
    asm volatile("mma.sync.aligned.m16n8k16.row.col.f32.bf16.bf16.f32 "
        "{%0,%1,%2,%3}, {%4,%5,%6,%7}, {%8,%9}, {%0,%1,%2,%3};"
        : "+f"(d[0]), "+f"(d[1]), "+f"(d[2]), "+f"(d[3])
        : "r"(a[0]), "r"(a[1]), "r"(a[2]), "r"(a[3]), "r"(b[0]), "r"(b[1]));
}

// ================= tiny prepass kernels =================
__global__ void offsets_kernel(const int* __restrict__ num_objs) {
    if (threadIdx.x == 0) {
        int s = 0;
        for (int i = 0; i < BATCH; i++) { g_offs[i] = s; s += num_objs[i]; }
        g_offs[BATCH] = s;
    }
}

__global__ void bkv_kernel(const float* __restrict__ bk, const float* __restrict__ bv) {
    int i = blockIdx.x * blockDim.x + threadIdx.x;   // 4096
    int p = i >> 10, j = i & 1023;
    g_bkv[i] = (j < DM) ? bk[p * DM + j] : bv[p * DM + j - DM];
}

__global__ __launch_bounds__(256) void cvt_bf16_kernel(const float* __restrict__ X,
                                                       __nv_bfloat16* __restrict__ Y, int n4) {
    int i = blockIdx.x * blockDim.x + threadIdx.x;
    if (i < n4) {
        float4 v = ((const float4*)X)[i];
        __nv_bfloat162 a, b;
        a.x = __float2bfloat16_rn(v.x); a.y = __float2bfloat16_rn(v.y);
        b.x = __float2bfloat16_rn(v.z); b.y = __float2bfloat16_rn(v.w);
        ((__nv_bfloat162*)Y)[i * 2 + 0] = a;
        ((__nv_bfloat162*)Y)[i * 2 + 1] = b;
    }
}

// transpose + bf16 round: S[R x C] (per layer z) -> D[C x R]
__global__ __launch_bounds__(256) void transpose_bf16_kernel(
    const float* __restrict__ S, __nv_bfloat16* __restrict__ D,
    int R, int C, size_t sStride, size_t dStride)
{
    __shared__ float t[32][33];
    const float* Sp = S + blockIdx.z * sStride;
    __nv_bfloat16* Dp = D + blockIdx.z * dStride;
    int bx = blockIdx.x * 32;
    int by = blockIdx.y * 32;
    int x = bx + threadIdx.x;
#pragma unroll
    for (int yy = threadIdx.y; yy < 32; yy += 8)
        t[yy][threadIdx.x] = Sp[(size_t)(by + yy) * C + x];
    __syncthreads();
    int x2 = by + threadIdx.x;
#pragma unroll
    for (int yy = threadIdx.y; yy < 32; yy += 8)
        Dp[(size_t)(bx + yy) * R + x2] = __float2bfloat16_rn(t[threadIdx.x][yy]);
}

// ======== bf16 mma.sync GEMM: C = A[MxK] @ Bt[NxK]^T + bias (+R) (relu) ========
// CTA 128x128, BK=32 halves, 4-stage cp.async, 8 warps of 64x32, m16n8k16.
#define LDSH 40                            // padded row stride (halves)
#define TILEB (128 * LDSH * 2)             // 10240 B
#define STAGEB (2 * TILEB)                 // 20480 B
#define NSTAGE 4
#define GEMM_SMEM (NSTAGE * STAGEB)        // 81920 B

template <bool RELU, bool RESID, bool OF32, bool OBF16>
__global__ __launch_bounds__(256) void gemm_bf16_k(
    const __nv_bfloat16* __restrict__ A, const __nv_bfloat16* __restrict__ Bt,
    const float* __restrict__ bias, const float* __restrict__ R,
    float* __restrict__ C, __nv_bfloat16* __restrict__ Cb, int M, int K, int N)
{
    extern __shared__ char smem[];
    const uint32_t sb = smem_u32(smem);
    const int tid = threadIdx.x;
    const int lane = tid & 31;
    const int wid = tid >> 5;
    const int m0 = blockIdx.y * 128;
    const int n0 = blockIdx.x * 128;
    const int warp_m = wid & 1;
    const int warp_n = wid >> 1;

    float acc[4][4][4];
#pragma unroll
    for (int i = 0; i < 4; i++)
#pragma unroll
        for (int j = 0; j < 4; j++)
#pragma unroll
            for (int r = 0; r < 4; r++) acc[i][j][r] = 0.f;

    const int lmrow  = lane & 15;            // ldmatrix row within 16x16 tile
    const int lmbyte = (lane >> 4) * 16;     // col-half byte offset
    const int KT = K >> 5;

    auto load_stage = [&](int s, int kit) {
        const int k0 = kit << 5;
        const uint32_t base = sb + (uint32_t)s * STAGEB;
#pragma unroll
        for (int i = 0; i < 2; i++) {
            int c = tid + i * 256;           // 0..511
            int row = c >> 2, c16 = c & 3;
            int gr = m0 + row; gr = gr < M ? gr : M - 1;
            cp_async16(base + row * (LDSH * 2) + c16 * 16,
                       A + (size_t)gr * K + k0 + c16 * 8);
        }
#pragma unroll
        for (int i = 0; i < 2; i++) {
            int c = tid + i * 256;
            int row = c >> 2, c16 = c & 3;
            cp_async16(base + TILEB + row * (LDSH * 2) + c16 * 16,
                       Bt + (size_t)(n0 + row) * K + k0 + c16 * 8);
        }
        CP_COMMIT();
    };

#pragma unroll
    for (int s = 0; s < NSTAGE - 1; s++) load_stage(s, s);   // KT >= 16 always

    for (int it = 0; it < KT; it++) {
        int nk = it + NSTAGE - 1;
        if (nk < KT) load_stage(nk % NSTAGE, nk);
        else CP_COMMIT();
        CP_WAIT(NSTAGE - 2);
        __syncthreads();

        const uint32_t ab = sb + (uint32_t)(it % NSTAGE) * STAGEB;
        const uint32_t bb = ab + TILEB;

#pragma unroll
        for (int kk = 0; kk < 2; kk++) {
            uint32_t af[4][4];
#pragma unroll
            for (int mi = 0; mi < 4; mi++) {
                uint32_t addr = ab + (warp_m * 64 + mi * 16 + lmrow) * (LDSH * 2) + kk * 32 + lmbyte;
                ldmatrix_x4(af[mi][0], af[mi][1], af[mi][2], af[mi][3], addr);
            }
            uint32_t bf[4][2];
#pragma unroll
            for (int t = 0; t < 2; t++) {
                uint32_t addr = bb + (warp_n * 32 + t * 16 + lmrow) * (LDSH * 2) + kk * 32 + lmbyte;
                uint32_t r0, r1, r2, r3;
                ldmatrix_x4(r0, r1, r2, r3, addr);
                bf[t * 2 + 0][0] = r0; bf[t * 2 + 0][1] = r2;
                bf[t * 2 + 1][0] = r1; bf[t * 2 + 1][1] = r3;
            }
#pragma unroll
            for (int mi = 0; mi < 4; mi++)
#pragma unroll
                for (int nj = 0; nj < 4; nj++)
                    mma_bf16(acc[mi][nj], af[mi], bf[nj]);
        }
        __syncthreads();
    }

    // ---- epilogue ----
    const int er = lane >> 2;
    const int ec = (lane & 3) * 2;
#pragma unroll
    for (int mi = 0; mi < 4; mi++) {
#pragma unroll
        for (int half = 0; half < 2; half++) {
            int row = m0 + warp_m * 64 + mi * 16 + half * 8 + er;
            if (row >= M) continue;
#pragma unroll
            for (int nj = 0; nj < 4; nj++) {
                int col = n0 + warp_n * 32 + nj * 8 + ec;
                float2 v;
                v.x = acc[mi][nj][half * 2 + 0] + bias[col + 0];
                v.y = acc[mi][nj][half * 2 + 1] + bias[col + 1];
                if (RESID) {
                    const float2 rv = *(const float2*)(R + (size_t)row * N + col);
                    v.x += rv.x; v.y += rv.y;
                }
                if (RELU) { v.x = fmaxf(v.x, 0.f); v.y = fmaxf(v.y, 0.f); }
                if (OF32)
                    *(float2*)(C + (size_t)row * N + col) = v;
                if (OBF16) {
                    __nv_bfloat162 h2;
                    h2.x = __float2bfloat16_rn(v.x);
                    h2.y = __float2bfloat16_rn(v.y);
                    *(__nv_bfloat162*)(Cb + (size_t)row * N + col) = h2;
                }
            }
        }
    }
}

// ================= LayerNorm over D=512 =================
template <bool ACC, bool BOUT>
__global__ __launch_bounds__(128) void ln_kernel(
    const float* __restrict__ X, const float* __restrict__ g,
    const float* __restrict__ b, float* __restrict__ out, __nv_bfloat16* __restrict__ outb)
{
    int row = blockIdx.x;
    int tid = threadIdx.x;
    const float4* x4 = (const float4*)(X + (size_t)row * DM);
    float4 v = x4[tid];

    __shared__ float sbuf[8];
    int wid = tid >> 5, lane = tid & 31;

    float s = v.x + v.y + v.z + v.w;
#pragma unroll
    for (int o = 16; o > 0; o >>= 1) s += __shfl_xor_sync(0xffffffffu, s, o);
    if (lane == 0) sbuf[wid] = s;
    __syncthreads();
    float mean = (sbuf[0] + sbuf[1] + sbuf[2] + sbuf[3]) * (1.0f / DM);
    __syncthreads();

    float dx0 = v.x - mean, dx1 = v.y - mean, dx2 = v.z - mean, dx3 = v.w - mean;
    float sq = dx0 * dx0 + dx1 * dx1 + dx2 * dx2 + dx3 * dx3;
#pragma unroll
    for (int o = 16; o > 0; o >>= 1) sq += __shfl_xor_sync(0xffffffffu, sq, o);
    if (lane == 0) sbuf[wid] = sq;
    __syncthreads();
    float var = (sbuf[0] + sbuf[1] + sbuf[2] + sbuf[3]) * (1.0f / DM);
    float rstd = rsqrtf(var + LNEPS);

    float4 gg = ((const float4*)g)[tid];
    float4 bb = ((const float4*)b)[tid];
    float4 y;
    y.x = dx0 * rstd * gg.x + bb.x;
    y.y = dx1 * rstd * gg.y + bb.y;
    y.z = dx2 * rstd * gg.z + bb.z;
    y.w = dx3 * rstd * gg.w + bb.w;

    float4* o4 = (float4*)(out + (size_t)row * DM);
    if (ACC) {
        float4 prev = o4[tid];
        y.x += prev.x; y.y += prev.y; y.z += prev.z; y.w += prev.w;
    }
    o4[tid] = y;
    if (BOUT) {
        __nv_bfloat162 a, c;
        a.x = __float2bfloat16_rn(y.x); a.y = __float2bfloat16_rn(y.y);
        c.x = __float2bfloat16_rn(y.z); c.y = __float2bfloat16_rn(y.w);
        ((__nv_bfloat162*)(outb + (size_t)row * DM))[tid * 2 + 0] = a;
        ((__nv_bfloat162*)(outb + (size_t)row * DM))[tid * 2 + 1] = c;
    }
}

// ================= segment attention (fp32, chunked online softmax) =================
__global__ __launch_bounds__(96) void attn_kernel()
{
    int s = blockIdx.x;
    int h = blockIdx.y;
    int off = g_offs[s];
    int L = g_offs[s + 1] - off;

    __shared__ float Ks[95 * DKH];
    __shared__ float Vs[95 * DKH];
    for (int idx = threadIdx.x; idx < L * 16; idx += 96) {
        int j = idx >> 4, d4 = idx & 15;
        const float4* kp = (const float4*)(g_KV + (size_t)(off + j) * (2 * DM) + h * DKH);
        const float4* vp = (const float4*)(g_KV + (size_t)(off + j) * (2 * DM) + DM + h * DKH);
        ((float4*)Ks)[j * 16 + d4] = kp[d4];
        ((float4*)Vs)[j * 16 + d4] = vp[d4];
    }
    __syncthreads();

    int i = threadIdx.x;
    if (i >= L) return;

    float q[DKH];
    const float4* qp = (const float4*)(g_Q + (size_t)(off + i) * DM + h * DKH);
#pragma unroll
    for (int t = 0; t < 16; t++) {
        float4 u = qp[t];
        q[4 * t + 0] = u.x; q[4 * t + 1] = u.y; q[4 * t + 2] = u.z; q[4 * t + 3] = u.w;
    }

    float m = -INFINITY, l = 0.f;
    float acc[DKH];
#pragma unroll
    for (int d = 0; d < DKH; d++) acc[d] = 0.f;

    for (int j0 = 0; j0 < L; j0 += 8) {
        int nj = L - j0; if (nj > 8) nj = 8;
        float sc[8];
#pragma unroll
        for (int jj = 0; jj < 8; jj++) {
            if (jj < nj) {
                const float4* kr = (const float4*)&Ks[(j0 + jj) * DKH];
                float sd = 0.f;
#pragma unroll
                for (int t = 0; t < 16; t++) {
                    float4 kv = kr[t];
                    sd = fmaf(q[4 * t + 0], kv.x, sd);
                    sd = fmaf(q[4 * t + 1], kv.y, sd);
                    sd = fmaf(q[4 * t + 2], kv.z, sd);
                    sd = fmaf(q[4 * t + 3], kv.w, sd);
                }
                sc[jj] = sd * 0.125f;
            } else sc[jj] = -INFINITY;
        }
        float cm = sc[0];
#pragma unroll
        for (int jj = 1; jj < 8; jj++) cm = fmaxf(cm, sc[jj]);
        float mn = fmaxf(m, cm);
        float corr = __expf(m - mn);          // 0 on first chunk
        l *= corr;
#pragma unroll
        for (int d = 0; d < DKH; d++) acc[d] *= corr;
#pragma unroll
        for (int jj = 0; jj < 8; jj++) {
            if (jj < nj) {
                float p = __expf(sc[jj] - mn);
                l += p;
                const float4* vr = (const float4*)&Vs[(j0 + jj) * DKH];
#pragma unroll
                for (int t = 0; t < 16; t++) {
                    float4 vv = vr[t];
                    acc[4 * t + 0] = fmaf(p, vv.x, acc[4 * t + 0]);
                    acc[4 * t + 1] = fmaf(p, vv.y, acc[4 * t + 1]);
                    acc[4 * t + 2] = fmaf(p, vv.z, acc[4 * t + 2]);
                    acc[4 * t + 3] = fmaf(p, vv.w, acc[4 * t + 3]);
                }
            }
        }
        m = mn;
    }

    float inv = 1.0f / l;
    __nv_bfloat162* o = (__nv_bfloat162*)(g_ctxb + (size_t)(off + i) * DM + h * DKH);
#pragma unroll
    for (int t = 0; t < 32; t++) {
        __nv_bfloat162 h2;
        h2.x = __float2bfloat16_rn(acc[2 * t + 0] * inv);
        h2.y = __float2bfloat16_rn(acc[2 * t + 1] * inv);
        o[t] = h2;
    }
}

// ================= host =================
extern "C" void kernel_launch(void* const* d_in, const int* in_sizes, int n_in,
                              void* d_out, int out_size)
{
    const float* vis  = (const float*)d_in[0];
    const float* txt  = (const float*)d_in[1];
    const float* Wq   = (const float*)d_in[2];
    const float* bq   = (const float*)d_in[3];
    const float* Wk   = (const float*)d_in[4];
    const float* bk   = (const float*)d_in[5];
    const float* Wv   = (const float*)d_in[6];
    const float* bv   = (const float*)d_in[7];
    const float* Wo   = (const float*)d_in[8];
    const float* bo   = (const float*)d_in[9];
    const float* g1   = (const float*)d_in[10];
    const float* be1  = (const float*)d_in[11];
    const float* W1   = (const float*)d_in[12];
    const float* b1   = (const float*)d_in[13];
    const float* W2   = (const float*)d_in[14];
    const float* b2   = (const float*)d_in[15];
    const float* g2   = (const float*)d_in[16];
    const float* be2  = (const float*)d_in[17];
    const int*   nobj = (const int*)d_in[18];
    float* out = (float*)d_out;

    float *Q, *KV, *T1, *OUT1, *BKV;
    __nv_bfloat16 *VISB, *TXTB, *CTXB, *OUT1B, *HB;
    __nv_bfloat16 *WqT, *WkvT, *WoT, *W1T, *W2T;
    cudaGetSymbolAddress((void**)&Q, g_Q);
    cudaGetSymbolAddress((void**)&KV, g_KV);
    cudaGetSymbolAddress((void**)&T1, g_t1);
    cudaGetSymbolAddress((void**)&OUT1, g_out1);
    cudaGetSymbolAddress((void**)&BKV, g_bkv);
    cudaGetSymbolAddress((void**)&VISB, g_visb);
    cudaGetSymbolAddress((void**)&TXTB, g_txtb);
    cudaGetSymbolAddress((void**)&CTXB, g_ctxb);
    cudaGetSymbolAddress((void**)&OUT1B, g_out1b);
    cudaGetSymbolAddress((void**)&HB, g_hb);
    cudaGetSymbolAddress((void**)&WqT, g_WqT);
    cudaGetSymbolAddress((void**)&WkvT, g_WkvT);
    cudaGetSymbolAddress((void**)&WoT, g_WoT);
    cudaGetSymbolAddress((void**)&W1T, g_W1T);
    cudaGetSymbolAddress((void**)&W2T, g_W2T);

    cudaFuncSetAttribute(gemm_bf16_k<false, false, true,  false>, cudaFuncAttributeMaxDynamicSharedMemorySize, GEMM_SMEM);
    cudaFuncSetAttribute(gemm_bf16_k<false, true,  true,  false>, cudaFuncAttributeMaxDynamicSharedMemorySize, GEMM_SMEM);
    cudaFuncSetAttribute(gemm_bf16_k<true,  false, false, true >, cudaFuncAttributeMaxDynamicSharedMemorySize, GEMM_SMEM);

    offsets_kernel<<<1, 32>>>(nobj);
    bkv_kernel<<<16, 256>>>(bk, bv);

    const int NC4 = NTOK * DM / 4;
    cvt_bf16_kernel<<<(NC4 + 255) / 256, 256>>>(vis, VISB, NC4);
    cvt_bf16_kernel<<<(NC4 + 255) / 256, 256>>>(txt, TXTB, NC4);

    dim3 tb(32, 8);
    transpose_bf16_kernel<<<dim3(16, 16, 4), tb>>>(Wq, WqT, DM, DM, (size_t)DM * DM, (size_t)DM * DM);
    transpose_bf16_kernel<<<dim3(16, 16, 4), tb>>>(Wk, WkvT, DM, DM, (size_t)DM * DM, (size_t)2 * DM * DM);
    transpose_bf16_kernel<<<dim3(16, 16, 4), tb>>>(Wv, WkvT + (size_t)DM * DM, DM, DM, (size_t)DM * DM, (size_t)2 * DM * DM);
    transpose_bf16_kernel<<<dim3(16, 16, 4), tb>>>(Wo, WoT, DM, DM, (size_t)DM * DM, (size_t)DM * DM);
    transpose_bf16_kernel<<<dim3(64, 16, 4), tb>>>(W1, W1T, DM, DI, (size_t)DM * DI, (size_t)DI * DM);
    transpose_bf16_kernel<<<dim3(16, 64, 4), tb>>>(W2, W2T, DI, DM, (size_t)DI * DM, (size_t)DM * DI);

    const int MT = (NTOK + 127) / 128;   // 105
    dim3 gQ(DM / 128, MT);               // (4, 105)
    dim3 gKV(2 * DM / 128, MT);          // (8, 105)
    dim3 gFF1(DI / 128, MT);             // (16, 105)
    dim3 gAttn(BATCH, NH);

    struct Enc { const float* qs; const __nv_bfloat16* qsb; const __nv_bfloat16* kvb; int p; float* reg; bool first; };
    Enc encs[4] = {
        { vis, VISB, VISB, 0, out,                     true  },
        { vis, VISB, TXTB, 2, out,                     false },
        { txt, TXTB, TXTB, 1, out + (size_t)NTOK * DM, true  },
        { txt, TXTB, VISB, 3, out + (size_t)NTOK * DM, false },
    };

    for (int e = 0; e < 4; e++) {
        const float* qs = encs[e].qs;
        const __nv_bfloat16* qsb = encs[e].qsb;
        const __nv_bfloat16* kvb = encs[e].kvb;
        int p = encs[e].p;
        float* reg = encs[e].reg;

        const __nv_bfloat16* WqTp  = WqT  + (size_t)p * DM * DM;
        const __nv_bfloat16* WkvTp = WkvT + (size_t)p * 2 * DM * DM;
        const __nv_bfloat16* WoTp  = WoT  + (size_t)p * DM * DM;
        const __nv_bfloat16* W1Tp  = W1T  + (size_t)p * DI * DM;
        const __nv_bfloat16* W2Tp  = W2T  + (size_t)p * DM * DI;

        gemm_bf16_k<false, false, true, false><<<gQ, 256, GEMM_SMEM>>>(
            qsb, WqTp, bq + p * DM, nullptr, Q, nullptr, NTOK, DM, DM);
        gemm_bf16_k<false, false, true, false><<<gKV, 256, GEMM_SMEM>>>(
            kvb, WkvTp, BKV + p * 2 * DM, nullptr, KV, nullptr, NTOK, DM, 2 * DM);

        attn_kernel<<<gAttn, 96>>>();

        gemm_bf16_k<false, true, true, false><<<gQ, 256, GEMM_SMEM>>>(
            CTXB, WoTp, bo + p * DM, qs, T1, nullptr, NTOK, DM, DM);
        ln_kernel<false, true><<<NTOK, 128>>>(T1, g1 + p * DM, be1 + p * DM, OUT1, OUT1B);

        gemm_bf16_k<true, false, false, true><<<gFF1, 256, GEMM_SMEM>>>(
            OUT1B, W1Tp, b1 + p * DI, nullptr, nullptr, HB, NTOK, DM, DI);
        gemm_bf16_k<false, true, true, false><<<gQ, 256, GEMM_SMEM>>>(
            HB, W2Tp, b2 + p * DM, OUT1, T1, nullptr, NTOK, DI, DM);

        if (encs[e].first)
            ln_kernel<false, false><<<NTOK, 128>>>(T1, g2 + p * DM, be2 + p * DM, reg, nullptr);
        else
            ln_kernel<true, false><<<NTOK, 128>>>(T1, g2 + p * DM, be2 + p * DM, reg, nullptr);
    }
}

// round 5
// speedup vs baseline: 5.1340x; 1.0859x over previous
#include <cuda_runtime.h>
#include <cuda_bf16.h>
#include <math.h>
#include <stdint.h>

#define NTOK 13320
#define BATCH 240
#define DM 512
#define DI 2048
#define NH 8
#define DKH 64
#define LNEPS 1e-5f
#define NQ 1024
#define NKV 2048

typedef unsigned long long u64;

// ================= scratch (static device globals; no allocation) =================
__device__ float g_Q4 [2 * NTOK * NQ];          // [src][row][half*512+col]
__device__ float g_KV4[2 * NTOK * NKV];         // [src][row][half*1024 + (K|V)*512 + col]
__device__ float g_t14  [4 * NTOK * DM];
__device__ float g_out14[4 * NTOK * DM];
__device__ float g_out4s[4 * NTOK * DM];
__device__ int   g_offs[BATCH + 1];
__device__ float g_bq4 [2 * NQ];
__device__ float g_bkv4[2 * NKV];

__device__ __nv_bfloat16 g_visb  [NTOK * DM];
__device__ __nv_bfloat16 g_txtb  [NTOK * DM];
__device__ __nv_bfloat16 g_ctxb4 [4 * NTOK * DM];
__device__ __nv_bfloat16 g_out1b4[4 * NTOK * DM];
__device__ __nv_bfloat16 g_hb4   [4 * NTOK * DI];

__device__ __nv_bfloat16 g_WqT4 [2 * NQ * DM];
__device__ __nv_bfloat16 g_WkvT4[2 * NKV * DM];
__device__ __nv_bfloat16 g_WoT  [4 * DM * DM];
__device__ __nv_bfloat16 g_W1T  [4 * DI * DM];
__device__ __nv_bfloat16 g_W2T  [4 * DM * DI];

// ================= helpers =================
__device__ __forceinline__ uint32_t smem_u32(const void* p) {
    uint32_t a;
    asm("{ .reg .u64 t; cvta.to.shared.u64 t, %1; cvt.u32.u64 %0, t; }" : "=r"(a) : "l"(p));
    return a;
}
__device__ __forceinline__ void cp_async16(uint32_t dst, const void* src) {
    asm volatile("cp.async.cg.shared.global [%0], [%1], 16;" :: "r"(dst), "l"(src));
}
#define CP_COMMIT() asm volatile("cp.async.commit_group;" ::: "memory")
#define CP_WAIT(n)  asm volatile("cp.async.wait_group %0;" :: "n"(n) : "memory")

__device__ __forceinline__ void ldmatrix_x4(uint32_t& r0, uint32_t& r1, uint32_t& r2, uint32_t& r3, uint32_t addr) {
    asm volatile("ldmatrix.sync.aligned.m8n8.x4.shared.b16 {%0,%1,%2,%3}, [%4];"
        : "=r"(r0), "=r"(r1), "=r"(r2), "=r"(r3) : "r"(addr));
}
__device__ __forceinline__ void mma_bf16(float* d, const uint32_t* a, const uint32_t* b) {
    asm volatile("mma.sync.aligned.m16n8k16.row.col.f32.bf16.bf16.f32 "
        "{%0,%1,%2,%3}, {%4,%5,%6,%7}, {%8,%9}, {%0,%1,%2,%3};"
        : "+f"(d[0]), "+f"(d[1]), "+f"(d[2]), "+f"(d[3])
        : "r"(a[0]), "r"(a[1]), "r"(a[2]), "r"(a[3]), "r"(b[0]), "r"(b[1]));
}
__device__ __forceinline__ u64 q_at(const ulong4& q, int z) {
    u64 v;
    switch (z) { case 0: v = q.x; break; case 1: v = q.y; break;
                 case 2: v = q.z; break; default: v = q.w; }
    return v;
}

// ================= prepass kernels =================
__global__ void offsets_kernel(const int* __restrict__ num_objs) {
    if (threadIdx.x == 0) {
        int s = 0;
        for (int i = 0; i < BATCH; i++) { g_offs[i] = s; s += num_objs[i]; }
        g_offs[BATCH] = s;
    }
}

// build concatenated bias vectors bq4 / bkv4
__global__ void bias_concat_kernel(const float* __restrict__ bq, const float* __restrict__ bk,
                                   const float* __restrict__ bv) {
    int i = blockIdx.x * blockDim.x + threadIdx.x;     // 0..6143
    if (i < 2 * NQ) {
        int src = i >> 10, half = (i >> 9) & 1, j = i & 511;
        int p = src + 2 * half;                         // (0,0)->0 (0,1)->2 (1,0)->1 (1,1)->3
        g_bq4[i] = bq[p * DM + j];
    } else if (i < 2 * NQ + 2 * NKV) {
        int k = i - 2 * NQ;
        int src = k >> 11, r = k & 2047;
        int half = r >> 10, part = (r >> 9) & 1, j = r & 511;
        const int pt[2][2] = { {0, 3}, {2, 1} };        // [src][half]
        int p = pt[src][half];
        g_bkv4[k] = (part ? bv : bk)[p * DM + j];
    }
}

__global__ __launch_bounds__(256) void cvt_bf16_kernel(const float* __restrict__ X,
                                                       __nv_bfloat16* __restrict__ Y, int n4) {
    int i = blockIdx.x * blockDim.x + threadIdx.x;
    if (i < n4) {
        float4 v = ((const float4*)X)[i];
        __nv_bfloat162 a, b;
        a.x = __float2bfloat16_rn(v.x); a.y = __float2bfloat16_rn(v.y);
        b.x = __float2bfloat16_rn(v.z); b.y = __float2bfloat16_rn(v.w);
        ((__nv_bfloat162*)Y)[i * 2 + 0] = a;
        ((__nv_bfloat162*)Y)[i * 2 + 1] = b;
    }
}

// transpose + bf16 round with uniform z-strides (Wo/W1/W2)
__global__ __launch_bounds__(256) void transpose_bf16_kernel(
    const float* __restrict__ S, __nv_bfloat16* __restrict__ D,
    int R, int C, size_t sStride, size_t dStride)
{
    __shared__ float t[32][33];
    const float* Sp = S + blockIdx.z * sStride;
    __nv_bfloat16* Dp = D + blockIdx.z * dStride;
    int bx = blockIdx.x * 32, by = blockIdx.y * 32;
    int x = bx + threadIdx.x;
#pragma unroll
    for (int yy = threadIdx.y; yy < 32; yy += 8)
        t[yy][threadIdx.x] = Sp[(size_t)(by + yy) * C + x];
    __syncthreads();
    int x2 = by + threadIdx.x;
#pragma unroll
    for (int yy = threadIdx.y; yy < 32; yy += 8)
        Dp[(size_t)(bx + yy) * R + x2] = __float2bfloat16_rn(t[threadIdx.x][yy]);
}

// transpose 512x512 with per-z destination offsets (Wq/Wk/Wv -> concatenated buffers)
__global__ __launch_bounds__(256) void transpose_bf16_q_kernel(
    const float* __restrict__ S, __nv_bfloat16* __restrict__ D, ulong4 doff)
{
    __shared__ float t[32][33];
    const float* Sp = S + (size_t)blockIdx.z * DM * DM;
    __nv_bfloat16* Dp = D + q_at(doff, blockIdx.z);
    int bx = blockIdx.x * 32, by = blockIdx.y * 32;
    int x = bx + threadIdx.x;
#pragma unroll
    for (int yy = threadIdx.y; yy < 32; yy += 8)
        t[yy][threadIdx.x] = Sp[(size_t)(by + yy) * DM + x];
    __syncthreads();
    int x2 = by + threadIdx.x;
#pragma unroll
    for (int yy = threadIdx.y; yy < 32; yy += 8)
        Dp[(size_t)(bx + yy) * DM + x2] = __float2bfloat16_rn(t[threadIdx.x][yy]);
}

// ======== bf16 mma.sync GEMM, z-batched via pointer quads ========
#define LDSH 40
#define TILEB (128 * LDSH * 2)
#define STAGEB (2 * TILEB)
#define NSTAGE 4
#define GEMM_SMEM (NSTAGE * STAGEB)     // 81920

template <bool RELU, bool RESID, bool OF32, bool OBF16>
__global__ __launch_bounds__(256) void gemm_bf16_k(
    ulong4 Aq, ulong4 Btq, ulong4 biasq, ulong4 Rq,
    float* __restrict__ C, size_t cStr, __nv_bfloat16* __restrict__ Cb, size_t cbStr,
    int M, int K, int N)
{
    extern __shared__ char smem[];
    const uint32_t sb = smem_u32(smem);
    const int tid = threadIdx.x;
    const int lane = tid & 31;
    const int wid = tid >> 5;
    const int z = blockIdx.z;
    const int m0 = blockIdx.y * 128;
    const int n0 = blockIdx.x * 128;
    const int warp_m = wid & 1;
    const int warp_n = wid >> 1;

    const __nv_bfloat16* A  = (const __nv_bfloat16*)q_at(Aq, z);
    const __nv_bfloat16* Bt = (const __nv_bfloat16*)q_at(Btq, z);
    const float* bias = (const float*)q_at(biasq, z);
    const float* R = RESID ? (const float*)q_at(Rq, z) : nullptr;
    if (OF32)  C  += (size_t)z * cStr;
    if (OBF16) Cb += (size_t)z * cbStr;

    float acc[4][4][4];
#pragma unroll
    for (int i = 0; i < 4; i++)
#pragma unroll
        for (int j = 0; j < 4; j++)
#pragma unroll
            for (int r = 0; r < 4; r++) acc[i][j][r] = 0.f;

    const int lmrow  = lane & 15;
    const int lmbyte = (lane >> 4) * 16;
    const int KT = K >> 5;

    auto load_stage = [&](int s, int kit) {
        const int k0 = kit << 5;
        const uint32_t base = sb + (uint32_t)s * STAGEB;
#pragma unroll
        for (int i = 0; i < 2; i++) {
            int c = tid + i * 256;
            int row = c >> 2, c16 = c & 3;
            int gr = m0 + row; gr = gr < M ? gr : M - 1;
            cp_async16(base + row * (LDSH * 2) + c16 * 16,
                       A + (size_t)gr * K + k0 + c16 * 8);
        }
#pragma unroll
        for (int i = 0; i < 2; i++) {
            int c = tid + i * 256;
            int row = c >> 2, c16 = c & 3;
            cp_async16(base + TILEB + row * (LDSH * 2) + c16 * 16,
                       Bt + (size_t)(n0 + row) * K + k0 + c16 * 8);
        }
        CP_COMMIT();
    };

#pragma unroll
    for (int s = 0; s < NSTAGE - 1; s++) load_stage(s, s);

    for (int it = 0; it < KT; it++) {
        int nk = it + NSTAGE - 1;
        if (nk < KT) load_stage(nk % NSTAGE, nk);
        else CP_COMMIT();
        CP_WAIT(NSTAGE - 2);
        __syncthreads();

        const uint32_t ab = sb + (uint32_t)(it % NSTAGE) * STAGEB;
        const uint32_t bb = ab + TILEB;

#pragma unroll
        for (int kk = 0; kk < 2; kk++) {
            uint32_t af[4][4];
#pragma unroll
            for (int mi = 0; mi < 4; mi++) {
                uint32_t addr = ab + (warp_m * 64 + mi * 16 + lmrow) * (LDSH * 2) + kk * 32 + lmbyte;
                ldmatrix_x4(af[mi][0], af[mi][1], af[mi][2], af[mi][3], addr);
            }
            uint32_t bf[4][2];
#pragma unroll
            for (int t = 0; t < 2; t++) {
                uint32_t addr = bb + (warp_n * 32 + t * 16 + lmrow) * (LDSH * 2) + kk * 32 + lmbyte;
                uint32_t r0, r1, r2, r3;
                ldmatrix_x4(r0, r1, r2, r3, addr);
                bf[t * 2 + 0][0] = r0; bf[t * 2 + 0][1] = r2;
                bf[t * 2 + 1][0] = r1; bf[t * 2 + 1][1] = r3;
            }
#pragma unroll
            for (int mi = 0; mi < 4; mi++)
#pragma unroll
                for (int nj = 0; nj < 4; nj++)
                    mma_bf16(acc[mi][nj], af[mi], bf[nj]);
        }
        __syncthreads();
    }

    const int er = lane >> 2;
    const int ec = (lane & 3) * 2;
#pragma unroll
    for (int mi = 0; mi < 4; mi++) {
#pragma unroll
        for (int half = 0; half < 2; half++) {
            int row = m0 + warp_m * 64 + mi * 16 + half * 8 + er;
            if (row >= M) continue;
#pragma unroll
            for (int nj = 0; nj < 4; nj++) {
                int col = n0 + warp_n * 32 + nj * 8 + ec;
                float2 v;
                v.x = acc[mi][nj][half * 2 + 0] + bias[col + 0];
                v.y = acc[mi][nj][half * 2 + 1] + bias[col + 1];
                if (RESID) {
                    const float2 rv = *(const float2*)(R + (size_t)row * N + col);
                    v.x += rv.x; v.y += rv.y;
                }
                if (RELU) { v.x = fmaxf(v.x, 0.f); v.y = fmaxf(v.y, 0.f); }
                if (OF32)
                    *(float2*)(C + (size_t)row * N + col) = v;
                if (OBF16) {
                    __nv_bfloat162 h2;
                    h2.x = __float2bfloat16_rn(v.x);
                    h2.y = __float2bfloat16_rn(v.y);
                    *(__nv_bfloat162*)(Cb + (size_t)row * N + col) = h2;
                }
            }
        }
    }
}

// ================= LayerNorm (z-batched) =================
template <bool BOUT>
__global__ __launch_bounds__(128) void ln_kernel(
    const float* __restrict__ X, size_t xStr, ulong4 gq, ulong4 bq,
    float* __restrict__ out, size_t oStr, __nv_bfloat16* __restrict__ outb, size_t obStr)
{
    int row = blockIdx.x;
    int e = blockIdx.y;
    int tid = threadIdx.x;
    X += (size_t)e * xStr;
    out += (size_t)e * oStr;
    const float* g = (const float*)q_at(gq, e);
    const float* b = (const float*)q_at(bq, e);

    const float4* x4 = (const float4*)(X + (size_t)row * DM);
    float4 v = x4[tid];

    __shared__ float sbuf[8];
    int wid = tid >> 5, lane = tid & 31;

    float s = v.x + v.y + v.z + v.w;
#pragma unroll
    for (int o = 16; o > 0; o >>= 1) s += __shfl_xor_sync(0xffffffffu, s, o);
    if (lane == 0) sbuf[wid] = s;
    __syncthreads();
    float mean = (sbuf[0] + sbuf[1] + sbuf[2] + sbuf[3]) * (1.0f / DM);
    __syncthreads();

    float dx0 = v.x - mean, dx1 = v.y - mean, dx2 = v.z - mean, dx3 = v.w - mean;
    float sq = dx0 * dx0 + dx1 * dx1 + dx2 * dx2 + dx3 * dx3;
#pragma unroll
    for (int o = 16; o > 0; o >>= 1) sq += __shfl_xor_sync(0xffffffffu, sq, o);
    if (lane == 0) sbuf[wid] = sq;
    __syncthreads();
    float var = (sbuf[0] + sbuf[1] + sbuf[2] + sbuf[3]) * (1.0f / DM);
    float rstd = rsqrtf(var + LNEPS);

    float4 gg = ((const float4*)g)[tid];
    float4 bb = ((const float4*)b)[tid];
    float4 y;
    y.x = dx0 * rstd * gg.x + bb.x;
    y.y = dx1 * rstd * gg.y + bb.y;
    y.z = dx2 * rstd * gg.z + bb.z;
    y.w = dx3 * rstd * gg.w + bb.w;

    ((float4*)(out + (size_t)row * DM))[tid] = y;
    if (BOUT) {
        __nv_bfloat16* ob = outb + (size_t)e * obStr + (size_t)row * DM;
        __nv_bfloat162 a, c;
        a.x = __float2bfloat16_rn(y.x); a.y = __float2bfloat16_rn(y.y);
        c.x = __float2bfloat16_rn(y.z); c.y = __float2bfloat16_rn(y.w);
        ((__nv_bfloat162*)ob)[tid * 2 + 0] = a;
        ((__nv_bfloat162*)ob)[tid * 2 + 1] = c;
    }
}

// ================= segment attention (all 4 encoders, grid.z = enc) =================
__global__ __launch_bounds__(96) void attn_kernel()
{
    int s = blockIdx.x;
    int h = blockIdx.y;
    int e = blockIdx.z;
    int off = g_offs[s];
    int L = g_offs[s + 1] - off;

    const int srcQ = e >> 1, halfQ = e & 1;
    const int srcKV_t[4]  = {0, 1, 1, 0};
    const int halfKV_t[4] = {0, 0, 1, 1};
    const int srcKV = srcKV_t[e], halfKV = halfKV_t[e];

    const float* Qbase  = g_Q4  + (size_t)srcQ  * NTOK * NQ  + halfQ  * DM + h * DKH;
    const float* Kbase  = g_KV4 + (size_t)srcKV * NTOK * NKV + halfKV * NQ + h * DKH;
    const float* Vbase  = Kbase + DM;

    __shared__ float Ks[95 * DKH];
    __shared__ float Vs[95 * DKH];
    for (int idx = threadIdx.x; idx < L * 16; idx += 96) {
        int j = idx >> 4, d4 = idx & 15;
        ((float4*)Ks)[j * 16 + d4] = ((const float4*)(Kbase + (size_t)(off + j) * NKV))[d4];
        ((float4*)Vs)[j * 16 + d4] = ((const float4*)(Vbase + (size_t)(off + j) * NKV))[d4];
    }
    __syncthreads();

    int i = threadIdx.x;
    if (i >= L) return;

    float q[DKH];
    const float4* qp = (const float4*)(Qbase + (size_t)(off + i) * NQ);
#pragma unroll
    for (int t = 0; t < 16; t++) {
        float4 u = qp[t];
        q[4 * t + 0] = u.x; q[4 * t + 1] = u.y; q[4 * t + 2] = u.z; q[4 * t + 3] = u.w;
    }

    float m = -INFINITY, l = 0.f;
    float acc[DKH];
#pragma unroll
    for (int d = 0; d < DKH; d++) acc[d] = 0.f;

    for (int j0 = 0; j0 < L; j0 += 8) {
        int nj = L - j0; if (nj > 8) nj = 8;
        float sc[8];
#pragma unroll
        for (int jj = 0; jj < 8; jj++) {
            if (jj < nj) {
                const float4* kr = (const float4*)&Ks[(j0 + jj) * DKH];
                float sd = 0.f;
#pragma unroll
                for (int t = 0; t < 16; t++) {
                    float4 kv = kr[t];
                    sd = fmaf(q[4 * t + 0], kv.x, sd);
                    sd = fmaf(q[4 * t + 1], kv.y, sd);
                    sd = fmaf(q[4 * t + 2], kv.z, sd);
                    sd = fmaf(q[4 * t + 3], kv.w, sd);
                }
                sc[jj] = sd * 0.125f;
            } else sc[jj] = -INFINITY;
        }
        float cm = sc[0];
#pragma unroll
        for (int jj = 1; jj < 8; jj++) cm = fmaxf(cm, sc[jj]);
        float mn = fmaxf(m, cm);
        float corr = __expf(m - mn);
        l *= corr;
#pragma unroll
        for (int d = 0; d < DKH; d++) acc[d] *= corr;
#pragma unroll
        for (int jj = 0; jj < 8; jj++) {
            if (jj < nj) {
                float p = __expf(sc[jj] - mn);
                l += p;
                const float4* vr = (const float4*)&Vs[(j0 + jj) * DKH];
#pragma unroll
                for (int t = 0; t < 16; t++) {
                    float4 vv = vr[t];
                    acc[4 * t + 0] = fmaf(p, vv.x, acc[4 * t + 0]);
                    acc[4 * t + 1] = fmaf(p, vv.y, acc[4 * t + 1]);
                    acc[4 * t + 2] = fmaf(p, vv.z, acc[4 * t + 2]);
                    acc[4 * t + 3] = fmaf(p, vv.w, acc[4 * t + 3]);
                }
            }
        }
        m = mn;
    }

    float inv = 1.0f / l;
    __nv_bfloat162* o = (__nv_bfloat162*)(g_ctxb4 + (size_t)e * NTOK * DM + (size_t)(off + i) * DM + h * DKH);
#pragma unroll
    for (int t = 0; t < 32; t++) {
        __nv_bfloat162 h2;
        h2.x = __float2bfloat16_rn(acc[2 * t + 0] * inv);
        h2.y = __float2bfloat16_rn(acc[2 * t + 1] * inv);
        o[t] = h2;
    }
}

// ================= final sum: out = [s0+s1 ; s2+s3] =================
__global__ __launch_bounds__(256) void sum_kernel(float* __restrict__ out) {
    const int half4 = NTOK * DM / 4;
    int i = blockIdx.x * blockDim.x + threadIdx.x;
    if (i >= 2 * half4) return;
    const float4* s = (const float4*)g_out4s;
    float4 a, b;
    if (i < half4) { a = s[i]; b = s[i + half4]; }
    else { a = s[i + half4]; b = s[i + 2 * half4]; }
    float4 v; v.x = a.x + b.x; v.y = a.y + b.y; v.z = a.z + b.z; v.w = a.w + b.w;
    ((float4*)out)[i] = v;
}

// ================= host =================
extern "C" void kernel_launch(void* const* d_in, const int* in_sizes, int n_in,
                              void* d_out, int out_size)
{
    const float* vis  = (const float*)d_in[0];
    const float* txt  = (const float*)d_in[1];
    const float* Wq   = (const float*)d_in[2];
    const float* bq   = (const float*)d_in[3];
    const float* Wk   = (const float*)d_in[4];
    const float* bk   = (const float*)d_in[5];
    const float* Wv   = (const float*)d_in[6];
    const float* bv   = (const float*)d_in[7];
    const float* Wo   = (const float*)d_in[8];
    const float* bo   = (const float*)d_in[9];
    const float* g1   = (const float*)d_in[10];
    const float* be1  = (const float*)d_in[11];
    const float* W1   = (const float*)d_in[12];
    const float* b1   = (const float*)d_in[13];
    const float* W2   = (const float*)d_in[14];
    const float* b2   = (const float*)d_in[15];
    const float* g2   = (const float*)d_in[16];
    const float* be2  = (const float*)d_in[17];
    const int*   nobj = (const int*)d_in[18];
    float* out = (float*)d_out;

    float *Q4, *KV4, *T14, *OUT14, *OUT4S, *BQ4, *BKV4;
    __nv_bfloat16 *VISB, *TXTB, *CTXB4, *OUT1B4, *HB4;
    __nv_bfloat16 *WqT4, *WkvT4, *WoT, *W1T, *W2T;
    cudaGetSymbolAddress((void**)&Q4, g_Q4);
    cudaGetSymbolAddress((void**)&KV4, g_KV4);
    cudaGetSymbolAddress((void**)&T14, g_t14);
    cudaGetSymbolAddress((void**)&OUT14, g_out14);
    cudaGetSymbolAddress((void**)&OUT4S, g_out4s);
    cudaGetSymbolAddress((void**)&BQ4, g_bq4);
    cudaGetSymbolAddress((void**)&BKV4, g_bkv4);
    cudaGetSymbolAddress((void**)&VISB, g_visb);
    cudaGetSymbolAddress((void**)&TXTB, g_txtb);
    cudaGetSymbolAddress((void**)&CTXB4, g_ctxb4);
    cudaGetSymbolAddress((void**)&OUT1B4, g_out1b4);
    cudaGetSymbolAddress((void**)&HB4, g_hb4);
    cudaGetSymbolAddress((void**)&WqT4, g_WqT4);
    cudaGetSymbolAddress((void**)&WkvT4, g_WkvT4);
    cudaGetSymbolAddress((void**)&WoT, g_WoT);
    cudaGetSymbolAddress((void**)&W1T, g_W1T);
    cudaGetSymbolAddress((void**)&W2T, g_W2T);

    cudaFuncSetAttribute(gemm_bf16_k<false, false, true,  false>, cudaFuncAttributeMaxDynamicSharedMemorySize, GEMM_SMEM);
    cudaFuncSetAttribute(gemm_bf16_k<false, true,  true,  false>, cudaFuncAttributeMaxDynamicSharedMemorySize, GEMM_SMEM);
    cudaFuncSetAttribute(gemm_bf16_k<true,  false, false, true >, cudaFuncAttributeMaxDynamicSharedMemorySize, GEMM_SMEM);

    auto U4 = [](const void* a, const void* b, const void* c, const void* d) {
        ulong4 u; u.x = (u64)a; u.y = (u64)b; u.z = (u64)c; u.w = (u64)d; return u;
    };

    offsets_kernel<<<1, 32>>>(nobj);
    bias_concat_kernel<<<24, 256>>>(bq, bk, bv);

    const int NC4 = NTOK * DM / 4;
    cvt_bf16_kernel<<<(NC4 + 255) / 256, 256>>>(vis, VISB, NC4);
    cvt_bf16_kernel<<<(NC4 + 255) / 256, 256>>>(txt, TXTB, NC4);

    dim3 tb(32, 8);
    const size_t BLK = (size_t)DM * DM;       // 262144
    // Wq: p -> (src,half): p0(0,0) p1(1,0) p2(0,1) p3(1,1); dst off = src*1024*512 + half*BLK
    {
        ulong4 doff; doff.x = 0; doff.y = 2 * BLK; doff.z = BLK; doff.w = 3 * BLK;
        transpose_bf16_q_kernel<<<dim3(16, 16, 4), tb>>>(Wq, WqT4, doff);
    }
    // Wk/Wv into WkvT4 [src][2048][512]: src0: half0=p0, half1=p3; src1: half0=p2, half1=p1
    {
        ulong4 dk; dk.x = 0;        dk.y = 6 * BLK; dk.z = 4 * BLK; dk.w = 2 * BLK;
        ulong4 dv; dv.x = BLK;      dv.y = 7 * BLK; dv.z = 5 * BLK; dv.w = 3 * BLK;
        transpose_bf16_q_kernel<<<dim3(16, 16, 4), tb>>>(Wk, WkvT4, dk);
        transpose_bf16_q_kernel<<<dim3(16, 16, 4), tb>>>(Wv, WkvT4, dv);
    }
    transpose_bf16_kernel<<<dim3(16, 16, 4), tb>>>(Wo, WoT, DM, DM, BLK, BLK);
    transpose_bf16_kernel<<<dim3(64, 16, 4), tb>>>(W1, W1T, DM, DI, (size_t)DM * DI, (size_t)DI * DM);
    transpose_bf16_kernel<<<dim3(16, 64, 4), tb>>>(W2, W2T, DI, DM, (size_t)DI * DM, (size_t)DM * DI);

    const int MT = (NTOK + 127) / 128;   // 105
    const size_t SL = (size_t)NTOK * DM;   // encoder slice (elements)
    const int perm[4] = {0, 2, 1, 3};      // enc -> param layer

    ulong4 nullq; nullq.x = nullq.y = nullq.z = nullq.w = 0;

    // --- QKV: 2 fused GEMMs, z in {vis, txt} ---
    {
        ulong4 Aq = U4(VISB, TXTB, VISB, TXTB);
        ulong4 Bq = U4(WqT4, WqT4 + (size_t)NQ * DM, nullptr, nullptr);
        ulong4 bq_ = U4(BQ4, BQ4 + NQ, nullptr, nullptr);
        gemm_bf16_k<false, false, true, false><<<dim3(NQ / 128, MT, 2), 256, GEMM_SMEM>>>(
            Aq, Bq, bq_, nullq, Q4, (size_t)NTOK * NQ, nullptr, 0, NTOK, DM, NQ);

        ulong4 Bkv = U4(WkvT4, WkvT4 + (size_t)NKV * DM, nullptr, nullptr);
        ulong4 bkv_ = U4(BKV4, BKV4 + NKV, nullptr, nullptr);
        gemm_bf16_k<false, false, true, false><<<dim3(NKV / 128, MT, 2), 256, GEMM_SMEM>>>(
            Aq, Bkv, bkv_, nullq, KV4, (size_t)NTOK * NKV, nullptr, 0, NTOK, DM, NKV);
    }

    // --- attention, all encoders ---
    attn_kernel<<<dim3(BATCH, NH, 4), 96>>>();

    // --- proj + residual (z = enc) ---
    {
        ulong4 Aq = U4(CTXB4, CTXB4 + SL, CTXB4 + 2 * SL, CTXB4 + 3 * SL);
        ulong4 Bq = U4(WoT + perm[0] * BLK, WoT + perm[1] * BLK, WoT + perm[2] * BLK, WoT + perm[3] * BLK);
        ulong4 bq_ = U4(bo + perm[0] * DM, bo + perm[1] * DM, bo + perm[2] * DM, bo + perm[3] * DM);
        ulong4 Rq = U4(vis, vis, txt, txt);
        gemm_bf16_k<false, true, true, false><<<dim3(DM / 128, MT, 4), 256, GEMM_SMEM>>>(
            Aq, Bq, bq_, Rq, T14, SL, nullptr, 0, NTOK, DM, DM);
    }
    // --- LN1 ---
    {
        ulong4 gq = U4(g1 + perm[0] * DM, g1 + perm[1] * DM, g1 + perm[2] * DM, g1 + perm[3] * DM);
        ulong4 bq_ = U4(be1 + perm[0] * DM, be1 + perm[1] * DM, be1 + perm[2] * DM, be1 + perm[3] * DM);
        ln_kernel<true><<<dim3(NTOK, 4), 128>>>(T14, SL, gq, bq_, OUT14, SL, OUT1B4, SL);
    }
    // --- FFN1 (relu, bf16 out) ---
    {
        ulong4 Aq = U4(OUT1B4, OUT1B4 + SL, OUT1B4 + 2 * SL, OUT1B4 + 3 * SL);
        const size_t WB = (size_t)DI * DM;
        ulong4 Bq = U4(W1T + perm[0] * WB, W1T + perm[1] * WB, W1T + perm[2] * WB, W1T + perm[3] * WB);
        ulong4 bq_ = U4(b1 + perm[0] * DI, b1 + perm[1] * DI, b1 + perm[2] * DI, b1 + perm[3] * DI);
        gemm_bf16_k<true, false, false, true><<<dim3(DI / 128, MT, 4), 256, GEMM_SMEM>>>(
            Aq, Bq, bq_, nullq, nullptr, 0, HB4, (size_t)NTOK * DI, NTOK, DM, DI);
    }
    // --- FFN2 + residual out1 ---
    {
        const size_t HL = (size_t)NTOK * DI;
        ulong4 Aq = U4(HB4, HB4 + HL, HB4 + 2 * HL, HB4 + 3 * HL);
        const size_t WB = (size_t)DM * DI;
        ulong4 Bq = U4(W2T + perm[0] * WB, W2T + perm[1] * WB, W2T + perm[2] * WB, W2T + perm[3] * WB);
        ulong4 bq_ = U4(b2 + perm[0] * DM, b2 + perm[1] * DM, b2 + perm[2] * DM, b2 + perm[3] * DM);
        ulong4 Rq = U4(OUT14, OUT14 + SL, OUT14 + 2 * SL, OUT14 + 3 * SL);
        gemm_bf16_k<false, true, true, false><<<dim3(DM / 128, MT, 4), 256, GEMM_SMEM>>>(
            Aq, Bq, bq_, Rq, T14, SL, nullptr, 0, NTOK, DI, DM);
    }
    // --- LN2 -> 4 slices ---
    {
        ulong4 gq = U4(g2 + perm[0] * DM, g2 + perm[1] * DM, g2 + perm[2] * DM, g2 + perm[3] * DM);
        ulong4 bq_ = U4(be2 + perm[0] * DM, be2 + perm[1] * DM, be2 + perm[2] * DM, be2 + perm[3] * DM);
        ln_kernel<false><<<dim3(NTOK, 4), 128>>>(T14, SL, gq, bq_, OUT4S, SL, nullptr, 0);
    }
    // --- final sum into d_out ---
    sum_kernel<<<(2 * NTOK * DM / 4 + 255) / 256, 256>>>(out);
}